// round 17
// baseline (speedup 1.0000x reference)
#include <cuda_runtime.h>
#include <cuda_fp16.h>
#include <cstdint>

// ---------------- problem constants ----------------
#define BATCH    4096
#define N_COL    100
#define N_COND   64
#define TOTAL    6400
#define N_RODT   1600
#define N_EST    160
#define N_FOREST 100
#define N_HID    128
#define N_CLASS  10
#define EPSV     1e-5f
#define SDH      136

// ---------------- device scratch ----------------
__device__ float  g_xT  [N_COL * BATCH];
__device__ __half g_wTh [N_RODT * BATCH];
__device__ __half g_Ehf [N_RODT * N_HID];
__device__ __half g_W1hf[N_HID * N_HID];
__device__ __half g_wc2h[N_HID * 16];
__device__ float  g_s1[N_HID], g_d1[N_HID];
__device__ float  g_s2[16],    g_d2[16];
__device__ __half g_Yh [(size_t)N_FOREST * BATCH * N_CLASS];
__device__ float2 g_part[10 * (BATCH * N_CLASS / 2)];

__device__ __forceinline__ void cpasync16(uint32_t dst, const void* src) {
    asm volatile("cp.async.cg.shared.global [%0], [%1], 16;" :: "r"(dst), "l"(src));
}
#define CP_COMMIT asm volatile("cp.async.commit_group;")
#define CP_WAIT0  asm volatile("cp.async.wait_group 0;")

__device__ __forceinline__ float fast_sigmoid(float z) {
    float t;
    asm("tanh.approx.f32 %0, %1;" : "=f"(t) : "f"(z * 0.5f));
    return fmaf(0.5f, t, 0.5f);
}

// =====================================================================
// k_pre: [0,1600) transpose x ; [1600,2400) conversions ; block 2400 folds
// =====================================================================
__global__ void k_pre(const float* __restrict__ x,
                      const float* __restrict__ E, const float* __restrict__ fc1w,
                      const float* __restrict__ ln1w, const float* __restrict__ fc2w,
                      const float* __restrict__ ln2w,
                      const float* __restrict__ fc1b, const float* __restrict__ ln1b,
                      const float* __restrict__ fc2b, const float* __restrict__ ln2b) {
    int bx = blockIdx.x;
    if (bx < 1600) {
        int i = bx * 256 + threadIdx.x;
        int c = i >> 12;
        int b = i & 4095;
        g_xT[i] = x[b * N_COL + c];
    } else if (bx < 2400) {
        int i = (bx - 1600) * 256 + threadIdx.x;
        if (i < N_RODT * N_HID) g_Ehf[i] = __float2half_rn(E[i]);
        if (i < N_HID * N_HID) {
            int d = i >> 7;
            g_W1hf[i] = __float2half_rn(fc1w[i] * ln1w[d]);
        }
        if (i < N_HID * 16) {
            int o = i >> 4, c = i & 15;
            g_wc2h[i] = __float2half_rn((c < 10) ? fc2w[o * 10 + c] * ln2w[o] : 0.f);
        }
    } else {
        int o = threadIdx.x;
        if (o < 128) {
            float ssum = 0.f, dsum = 0.f;
            for (int k = 0; k < 128; k++) {
                ssum += __half2float(__float2half_rn(fc1w[k * 128 + o] * ln1w[k]));
                dsum += fc1w[k * 128 + o] * ln1b[k];
            }
            g_s1[o] = ssum;
            g_d1[o] = dsum + fc1b[o];
            if (o < 10) {
                float s2 = 0.f, d2 = 0.f;
                for (int k = 0; k < 128; k++) {
                    s2 += __half2float(__float2half_rn(fc2w[k * 10 + o] * ln2w[k]));
                    d2 += ln2b[k] * fc2w[k * 10 + o];
                }
                g_s2[o] = s2;
                g_d2[o] = d2 + fc2b[o];
            } else if (o < 16) {
                g_s2[o] = 0.f; g_d2[o] = 0.f;
            }
        }
    }
}

// =====================================================================
// Kernel 1
// =====================================================================
__global__ void __launch_bounds__(256, 4)
k1_rodt(const float* __restrict__ w1, const float* __restrict__ b1,
        const int*   __restrict__ perm,
        const float* __restrict__ gn1w, const float* __restrict__ gn1b,
        const float* __restrict__ c2w,  const float* __restrict__ c2b,
        const float* __restrict__ gn2w, const float* __restrict__ gn2b,
        const float* __restrict__ c3w,  const float* __restrict__ c3b) {
    int g   = blockIdx.x;
    int tid = threadIdx.x;
    __shared__ int   sc[4];
    __shared__ float sw1[4], sb1[4], sg1w[4], sg1b[4];
    __shared__ float sw2[16], sb2[4], sg2w[4], sg2b[4], sw3[4], sb3;
    if (tid < 4) {
        int t = 4 * g + tid;
        int p = perm[t];
        int c = p % N_COL;
        int j = p / N_COL;
        sc [tid] = c;
        sw1[tid] = w1[c * N_COND + j];
        sb1[tid] = b1[c * N_COND + j];
        sg1w[tid] = gn1w[t];  sg1b[tid] = gn1b[t];
        sb2 [tid] = c2b[t];
        sg2w[tid] = gn2w[t];  sg2b[tid] = gn2b[t];
        sw3 [tid] = c3w[g * 4 + tid];
    }
    if (tid < 16) sw2[tid] = c2w[g * 16 + tid];
    if (tid == 31) sb3 = c3b[g];
    __syncthreads();

    const int b = blockIdx.y * 1024 + tid * 4;
    float4 xv[4];
#pragma unroll
    for (int k = 0; k < 4; k++)
        xv[k] = *(const float4*)&g_xT[sc[k] * BATCH + b];

    float out[4];
#pragma unroll
    for (int j = 0; j < 4; j++) {
        float v[4];
#pragma unroll
        for (int k = 0; k < 4; k++) {
            float xval = (&xv[k].x)[j];
            float z = fmaf(xval, sw1[k], sb1[k]);
            v[k] = fast_sigmoid(z);
        }
        float mu = 0.25f * (v[0] + v[1] + v[2] + v[3]);
        float var = 0.f;
#pragma unroll
        for (int k = 0; k < 4; k++) { float d = v[k] - mu; var += d * d; }
        var *= 0.25f;
        float rs = rsqrtf(var + EPSV);
        float n[4];
#pragma unroll
        for (int k = 0; k < 4; k++) n[k] = fmaf((v[k] - mu) * rs, sg1w[k], sg1b[k]);
        float h[4];
#pragma unroll
        for (int o = 0; o < 4; o++) {
            float a = sb2[o];
#pragma unroll
            for (int k = 0; k < 4; k++) a = fmaf(n[k], sw2[k * 4 + o], a);
            h[o] = fmaxf(a, 0.f);
        }
        float mu2 = 0.25f * (h[0] + h[1] + h[2] + h[3]);
        float var2 = 0.f;
#pragma unroll
        for (int k = 0; k < 4; k++) { float d = h[k] - mu2; var2 += d * d; }
        var2 *= 0.25f;
        float rs2 = rsqrtf(var2 + EPSV);
        float wo = sb3;
#pragma unroll
        for (int k = 0; k < 4; k++)
            wo = fmaf(fmaf((h[k] - mu2) * rs2, sg2w[k], sg2b[k]), sw3[k], wo);
        out[j] = wo;
    }
    __half2 e01 = __floats2half2_rn(__expf(out[0]), __expf(out[1]));
    __half2 e23 = __floats2half2_rn(__expf(out[2]), __expf(out[3]));
    uint2 pk;
    pk.x = *(uint32_t*)&e01;
    pk.y = *(uint32_t*)&e23;
    *(uint2*)&g_wTh[(size_t)g * BATCH + b] = pk;
}

// =====================================================================
// fp16 m16n8k16 mma + ldmatrix
// =====================================================================
__device__ __forceinline__ uint32_t smaddr(const void* p) {
    return (uint32_t)__cvta_generic_to_shared(p);
}
__device__ __forceinline__ void ldsm4t(uint32_t& r0, uint32_t& r1, uint32_t& r2, uint32_t& r3,
                                       uint32_t addr) {
    asm volatile("ldmatrix.sync.aligned.m8n8.x4.trans.shared.b16 {%0,%1,%2,%3}, [%4];"
                 : "=r"(r0), "=r"(r1), "=r"(r2), "=r"(r3) : "r"(addr));
}
__device__ __forceinline__ void ldsm2t(uint32_t& r0, uint32_t& r1, uint32_t addr) {
    asm volatile("ldmatrix.sync.aligned.m8n8.x2.trans.shared.b16 {%0,%1}, [%2];"
                 : "=r"(r0), "=r"(r1) : "r"(addr));
}
__device__ __forceinline__ void mma_f16(float* c, const uint32_t* a, const uint32_t* b) {
    asm volatile("mma.sync.aligned.m16n8k16.row.col.f32.f16.f16.f32 "
                 "{%0,%1,%2,%3}, {%4,%5,%6,%7}, {%8,%9}, {%0,%1,%2,%3};"
                 : "+f"(c[0]), "+f"(c[1]), "+f"(c[2]), "+f"(c[3])
                 : "r"(a[0]), "r"(a[1]), "r"(a[2]), "r"(a[3]), "r"(b[0]), "r"(b[1]));
}

// 16 warps, 32x32 warp tiles (R15-validated config)
template<int KSTEPS>
__device__ __forceinline__ void gemm_h(const __half* __restrict__ Asm,
                                       const __half* __restrict__ Bsm,
                                       int warp, int lane, float acc[2][4][4]) {
    const int M0 = (warp & 3) * 32, N0 = (warp >> 2) * 32;
    const int a_k = ((lane >> 4) << 3) + (lane & 7);
    const int a_m = ((lane >> 3) & 1) << 3;
    const int b_k = (((lane >> 3) & 1) << 3) + (lane & 7);
    const int b_n = (lane >> 4) << 3;
#pragma unroll
    for (int ks = 0; ks < KSTEPS; ks++) {
        const int K0 = ks * 16;
        uint32_t afr[2][4];
#pragma unroll
        for (int mt = 0; mt < 2; mt++) {
            uint32_t addr = smaddr(Asm + (K0 + a_k) * SDH + (M0 + mt * 16 + a_m));
            ldsm4t(afr[mt][0], afr[mt][1], afr[mt][2], afr[mt][3], addr);
        }
        uint32_t bfr[4][2];
#pragma unroll
        for (int np = 0; np < 2; np++) {
            uint32_t addr = smaddr(Bsm + (K0 + b_k) * SDH + (N0 + np * 16 + b_n));
            uint32_t r0, r1, r2, r3;
            ldsm4t(r0, r1, r2, r3, addr);
            bfr[np * 2][0] = r0;     bfr[np * 2][1] = r1;
            bfr[np * 2 + 1][0] = r2; bfr[np * 2 + 1][1] = r3;
        }
#pragma unroll
        for (int mt = 0; mt < 2; mt++)
#pragma unroll
            for (int nt = 0; nt < 4; nt++) mma_f16(acc[mt][nt], afr[mt], bfr[nt]);
    }
}

// =====================================================================
// k23: R15 config restored (512 threads, 2 blocks/SM), barrier-trimmed.
// =====================================================================
#define OFF_WH0 (160 * SDH * 2)
#define OFF_WH1 (OFF_WH0 + 80 * SDH * 2)
#define K23_SMEM (OFF_WH1 + 80 * SDH * 2)  // 87040
__global__ void __launch_bounds__(512, 2) k23_forest_mlp(const int* __restrict__ swr) {
    extern __shared__ char sh[];
    __half* Ph  = (__half*)sh;
    __half* Wh0 = (__half*)(sh + OFF_WH0);
    __half* Wh1 = (__half*)(sh + OFF_WH1);

    __shared__ int   s_idx[160];
    __shared__ float s_invS[128];
    __shared__ float s_scratch[2048];
    __shared__ float s_mu[128], s_rs[128];
    __shared__ float s_s1[128], s_d1[128];
    __shared__ __align__(16) __half s_wc2h[128 * 16];
    __shared__ float s_s2[16], s_d2[16];

    float* s_part = s_scratch;
    float* s_redA = s_scratch;
    float* s_redB = s_scratch + 1024;

    const int tid = threadIdx.x, lane = tid & 31, warp = tid >> 5;
    const int f = blockIdx.y;
    const int b0 = blockIdx.x * 128;

    if (tid < 160) s_idx[tid] = swr[f * N_EST + tid];
    __syncthreads();

    // ---- issue E half0 via cp.async ----
    {
        uint32_t wb0 = (uint32_t)__cvta_generic_to_shared(Wh0);
#pragma unroll
        for (int i = tid; i < 80 * 16; i += 512) {
            int e = i >> 4, q = i & 15;
            cpasync16(wb0 + e * (SDH * 2) + q * 16, g_Ehf + (size_t)s_idx[e] * N_HID + q * 8);
        }
        CP_COMMIT;
    }

    // ---- stage P + fused invS partials ----
    {
        float p0 = 0.f, p1 = 0.f, p2 = 0.f, p3 = 0.f;
        const int b4 = tid & 31;
#pragma unroll
        for (int j = 0; j < 10; j++) {
            int e = (tid >> 5) + 16 * j;
            uint2 pk = *(const uint2*)(g_wTh + (size_t)s_idx[e] * BATCH + b0 + b4 * 4);
            *(uint2*)(Ph + e * SDH + b4 * 4) = pk;
            float2 f01 = __half22float2(*(__half2*)&pk.x);
            float2 f23 = __half22float2(*(__half2*)&pk.y);
            p0 += f01.x; p1 += f01.y; p2 += f23.x; p3 += f23.y;
        }
        float* pp = s_part + warp * 128 + b4 * 4;
        pp[0] = p0; pp[1] = p1; pp[2] = p2; pp[3] = p3;
    }
    if (tid < 128) { s_s1[tid] = g_s1[tid]; s_d1[tid] = g_d1[tid]; }
    if (tid < 256) ((uint4*)s_wc2h)[tid] = ((const uint4*)g_wc2h)[tid];
    if (tid < 16) { s_s2[tid] = g_s2[tid]; s_d2[tid] = g_d2[tid]; }
    CP_WAIT0;
    __syncthreads();

    // ---- issue E half1 -> Wh1 ----
    {
        uint32_t wb1 = (uint32_t)__cvta_generic_to_shared(Wh1);
#pragma unroll
        for (int i = tid; i < 80 * 16; i += 512) {
            int e = i >> 4, q = i & 15;
            cpasync16(wb1 + e * (SDH * 2) + q * 16, g_Ehf + (size_t)s_idx[80 + e] * N_HID + q * 8);
        }
        CP_COMMIT;
    }

    // ---- invS finalize ----
    if (tid < 128) {
        float s = 0.f;
#pragma unroll
        for (int w = 0; w < 16; w++) s += s_part[w * 128 + tid];
        s_invS[tid] = 1.f / s;
    }

    // ---- GEMM A: K=160, two halves ----
    float acc[2][4][4];
#pragma unroll
    for (int mt = 0; mt < 2; mt++)
#pragma unroll
        for (int nt = 0; nt < 4; nt++)
#pragma unroll
            for (int r = 0; r < 4; r++) acc[mt][nt][r] = 0.f;
    gemm_h<5>(Wh0, Ph, warp, lane, acc);
    CP_WAIT0;
    __syncthreads();
    {
        uint32_t wb0 = (uint32_t)__cvta_generic_to_shared(Wh0);
#pragma unroll
        for (int i = tid; i < 64 * 16; i += 512) {
            int k = i >> 4, q = i & 15;
            cpasync16(wb0 + k * (SDH * 2) + q * 16, g_W1hf + k * N_HID + q * 8);
        }
        CP_COMMIT;
    }
    gemm_h<5>(Wh1, Ph + 80 * SDH, warp, lane, acc);
    __syncthreads();
    {
        uint32_t wb1 = (uint32_t)__cvta_generic_to_shared(Wh1);
#pragma unroll
        for (int i = tid; i < 64 * 16; i += 512) {
            int k = i >> 4, q = i & 15;
            cpasync16(wb1 + k * (SDH * 2) + q * 16, g_W1hf + (64 + k) * N_HID + q * 8);
        }
        CP_COMMIT;
    }
    // epilogue A
    {
        const int M0 = (warp & 3) * 32, N0 = (warp >> 2) * 32;
        const int g = lane >> 2, q2 = (lane & 3) * 2;
#pragma unroll
        for (int mt = 0; mt < 2; mt++)
#pragma unroll
            for (int nt = 0; nt < 4; nt++) {
                int row = M0 + mt * 16 + g, col = N0 + nt * 8 + q2;
                float i0 = s_invS[col], i1 = s_invS[col + 1];
                *(__half2*)(Ph + row * SDH + col) =
                    __floats2half2_rn(acc[mt][nt][0] * i0, acc[mt][nt][1] * i1);
                *(__half2*)(Ph + (row + 8) * SDH + col) =
                    __floats2half2_rn(acc[mt][nt][2] * i0, acc[mt][nt][3] * i1);
            }
    }
    CP_WAIT0;
    __syncthreads();

    // ---- stats1 pass ----
    {
        const int c2 = (tid & 63) * 2, q = tid >> 6;
        float s0 = 0.f, s1v = 0.f, q0 = 0.f, q1 = 0.f;
#pragma unroll 4
        for (int r = 0; r < 16; r++) {
            float2 fv = __half22float2(*(__half2*)(Ph + (q * 16 + r) * SDH + c2));
            s0 += fv.x; s1v += fv.y;
            q0 = fmaf(fv.x, fv.x, q0); q1 = fmaf(fv.y, fv.y, q1);
        }
        s_redA[q * 128 + c2] = s0;  s_redA[q * 128 + c2 + 1] = s1v;
        s_redB[q * 128 + c2] = q0;  s_redB[q * 128 + c2 + 1] = q1;
    }
    __syncthreads();
    if (tid < 128) {
        float s = 0.f, s2 = 0.f;
#pragma unroll
        for (int w = 0; w < 8; w++) { s += s_redA[w * 128 + tid]; s2 += s_redB[w * 128 + tid]; }
        float mu = s * (1.f / 128.f);
        float var = fmaxf(s2 * (1.f / 128.f) - mu * mu, 0.f);
        s_mu[tid] = mu;
        s_rs[tid] = rsqrtf(var + EPSV);
    }

    // ---- GEMM B ----
#pragma unroll
    for (int mt = 0; mt < 2; mt++)
#pragma unroll
        for (int nt = 0; nt < 4; nt++)
#pragma unroll
            for (int r = 0; r < 4; r++) acc[mt][nt][r] = 0.f;
    gemm_h<4>(Wh0, Ph, warp, lane, acc);
    gemm_h<4>(Wh1, Ph + 64 * SDH, warp, lane, acc);
    __syncthreads();

    // epilogue B
    {
        const int M0 = (warp & 3) * 32, N0 = (warp >> 2) * 32;
        const int g = lane >> 2, q2 = (lane & 3) * 2;
#pragma unroll
        for (int mt = 0; mt < 2; mt++)
#pragma unroll
            for (int nt = 0; nt < 4; nt++) {
                int row = M0 + mt * 16 + g, col = N0 + nt * 8 + q2;
                float s1a = s_s1[row], d1a = s_d1[row];
                float s1b = s_s1[row + 8], d1b = s_d1[row + 8];
                float mu0 = s_mu[col], rs0 = s_rs[col];
                float mu1 = s_mu[col + 1], rs1 = s_rs[col + 1];
                *(__half2*)(Ph + row * SDH + col) = __floats2half2_rn(
                    fmaxf(fmaf(rs0, acc[mt][nt][0] - mu0 * s1a, d1a), 0.f),
                    fmaxf(fmaf(rs1, acc[mt][nt][1] - mu1 * s1a, d1a), 0.f));
                *(__half2*)(Ph + (row + 8) * SDH + col) = __floats2half2_rn(
                    fmaxf(fmaf(rs0, acc[mt][nt][2] - mu0 * s1b, d1b), 0.f),
                    fmaxf(fmaf(rs1, acc[mt][nt][3] - mu1 * s1b, d1b), 0.f));
            }
    }
    __syncthreads();

    // ---- stats2 pass ----
    {
        const int c2 = (tid & 63) * 2, q = tid >> 6;
        float s0 = 0.f, s1v = 0.f, q0 = 0.f, q1 = 0.f;
#pragma unroll 4
        for (int r = 0; r < 16; r++) {
            float2 fv = __half22float2(*(__half2*)(Ph + (q * 16 + r) * SDH + c2));
            s0 += fv.x; s1v += fv.y;
            q0 = fmaf(fv.x, fv.x, q0); q1 = fmaf(fv.y, fv.y, q1);
        }
        s_redA[q * 128 + c2] = s0;  s_redA[q * 128 + c2 + 1] = s1v;
        s_redB[q * 128 + c2] = q0;  s_redB[q * 128 + c2 + 1] = q1;
    }
    __syncthreads();
    if (tid < 128) {
        float s = 0.f, s2 = 0.f;
#pragma unroll
        for (int w = 0; w < 8; w++) { s += s_redA[w * 128 + tid]; s2 += s_redB[w * 128 + tid]; }
        float mu = s * (1.f / 128.f);
        float var = fmaxf(s2 * (1.f / 128.f) - mu * mu, 0.f);
        s_mu[tid] = mu;
        s_rs[tid] = rsqrtf(var + EPSV);
    }

    // ---- fc2 via mma ----
    {
        float a2[4] = {0.f, 0.f, 0.f, 0.f};
        const int N0 = warp * 8;
        const int a_k = ((lane >> 4) << 3) + (lane & 7);
        const int a_m = ((lane >> 3) & 1) << 3;
        const int b_k = lane & 15;
#pragma unroll
        for (int ks = 0; ks < 8; ks++) {
            const int K0 = ks * 16;
            uint32_t af[4];
            ldsm4t(af[0], af[1], af[2], af[3], smaddr(s_wc2h + (K0 + a_k) * 16 + a_m));
            uint32_t bf[2];
            ldsm2t(bf[0], bf[1], smaddr(Ph + (K0 + b_k) * SDH + N0));
            mma_f16(a2, af, bf);
        }
        __syncthreads();
        const int g = lane >> 2, q2 = (lane & 3) * 2;
        const int bb = N0 + q2;
        float rs2a = s_rs[bb],     mu2a = s_mu[bb];
        float rs2b = s_rs[bb + 1], mu2b = s_mu[bb + 1];
        size_t Rb = ((size_t)f * BATCH + b0 + bb) * N_CLASS;
        {
            int c = g;
            g_Yh[Rb + c]           = __float2half_rn(fmaf(rs2a, a2[0] - mu2a * s_s2[c], s_d2[c]));
            g_Yh[Rb + N_CLASS + c] = __float2half_rn(fmaf(rs2b, a2[1] - mu2b * s_s2[c], s_d2[c]));
        }
        if (g < 2) {
            int c = g + 8;
            g_Yh[Rb + c]           = __float2half_rn(fmaf(rs2a, a2[2] - mu2a * s_s2[c], s_d2[c]));
            g_Yh[Rb + N_CLASS + c] = __float2half_rn(fmaf(rs2b, a2[3] - mu2b * s_s2[c], s_d2[c]));
        }
    }
}

// =====================================================================
// k4 two-stage
// =====================================================================
__global__ void k4a(void) {
    int i = blockIdx.x * 256 + threadIdx.x;
    int c = blockIdx.y;
    if (i < BATCH * N_CLASS / 2) {
        float s0 = 0.f, s1 = 0.f;
#pragma unroll
        for (int j = 0; j < 10; j++) {
            int fidx = c * 10 + j;
            __half2 v = *((const __half2*)(g_Yh + (size_t)fidx * (BATCH * N_CLASS)) + i);
            float2 fv = __half22float2(v);
            s0 += fv.x; s1 += fv.y;
        }
        g_part[(size_t)c * (BATCH * N_CLASS / 2) + i] = make_float2(s0, s1);
    }
}
__global__ void k4b(float* __restrict__ out) {
    int i = blockIdx.x * 256 + threadIdx.x;
    if (i < BATCH * N_CLASS / 2) {
        float s0 = 0.f, s1 = 0.f;
#pragma unroll
        for (int c = 0; c < 10; c++) {
            float2 p = g_part[(size_t)c * (BATCH * N_CLASS / 2) + i];
            s0 += p.x; s1 += p.y;
        }
        out[2 * i]     = s0 * (1.f / N_FOREST);
        out[2 * i + 1] = s1 * (1.f / N_FOREST);
    }
}

// =====================================================================
extern "C" void kernel_launch(void* const* d_in, const int* in_sizes, int n_in,
                              void* d_out, int out_size) {
    const float* x     = (const float*)d_in[0];
    const float* w1    = (const float*)d_in[1];
    const float* b1    = (const float*)d_in[2];
    const int*   perm  = (const int*)  d_in[3];
    const float* gn1w  = (const float*)d_in[4];
    const float* gn1b  = (const float*)d_in[5];
    const float* c2w   = (const float*)d_in[6];
    const float* c2b   = (const float*)d_in[7];
    const float* gn2w  = (const float*)d_in[8];
    const float* gn2b  = (const float*)d_in[9];
    const float* c3w   = (const float*)d_in[10];
    const float* c3b   = (const float*)d_in[11];
    const int*   swr   = (const int*)  d_in[12];
    const float* E     = (const float*)d_in[13];
    const float* ln1w  = (const float*)d_in[14];
    const float* ln1b  = (const float*)d_in[15];
    const float* fc1w  = (const float*)d_in[16];
    const float* fc1b  = (const float*)d_in[17];
    const float* ln2w  = (const float*)d_in[18];
    const float* ln2b  = (const float*)d_in[19];
    const float* fc2w  = (const float*)d_in[20];
    const float* fc2b  = (const float*)d_in[21];
    float* out = (float*)d_out;

    cudaFuncSetAttribute(k23_forest_mlp, cudaFuncAttributeMaxDynamicSharedMemorySize, K23_SMEM);

    k_pre<<<2401, 256>>>(x, E, fc1w, ln1w, fc2w, ln2w, fc1b, ln1b, fc2b, ln2b);
    k1_rodt<<<dim3(N_RODT, BATCH / 1024), 256>>>(w1, b1, perm, gn1w, gn1b,
                                                 c2w, c2b, gn2w, gn2b, c3w, c3b);
    k23_forest_mlp<<<dim3(BATCH / 128, N_FOREST), 512, K23_SMEM>>>(swr);
    k4a<<<dim3(BATCH * N_CLASS / 2 / 256, 10), 256>>>();
    k4b<<<BATCH * N_CLASS / 2 / 256, 256>>>(out);
}